// round 3
// baseline (speedup 1.0000x reference)
#include <cuda_runtime.h>

// CapsNet dynamic routing, fused, shuffle-free.
// b_t = u * Vsum  (Vsum = running sum of v) so u is never materialized.
// Thread = (batch, d); loops over the CTA's 16 input-caps, accumulating
// s[o] in registers. W tile broadcast from smem (warp = 32 b's, same d).

namespace {
constexpr int B_  = 256;
constexpr int IC_ = 1152;
constexpr int ID_ = 8;
constexpr int OC_ = 10;
constexpr int OD_ = 16;
constexpr int SOD = B_ * OD_ * OC_;   // 40960

constexpr int IBLK = 16;              // input caps per CTA
constexpr int BCH  = 64;              // batches per CTA
constexpr int NIB  = IC_ / IBLK;      // 72
constexpr int NBCH = B_ / BCH;        // 4

constexpr int W_TILE  = IBLK * OC_ * OD_ * ID_;   // 20480 floats (80 KB)
constexpr int X_TILE  = IBLK * BCH * ID_;         // 8192 floats  (32 KB)
constexpr int SMEMB   = (W_TILE + X_TILE) * 4;    // 114688 bytes
}

__device__ float g_s[3][SOD];    // s per iteration, layout [b][d][o]
__device__ float g_Vsum[SOD];    // running sum of v
__device__ float g_Vs[SOD];      // Vsum * log2(e)

__device__ __forceinline__ float fast_ex2(float x) {
    float y; asm("ex2.approx.ftz.f32 %0, %1;" : "=f"(y) : "f"(x)); return y;
}
__device__ __forceinline__ float fast_rcp(float x) {
    float y; asm("rcp.approx.ftz.f32 %0, %1;" : "=f"(y) : "f"(x)); return y;
}
__device__ __forceinline__ float fast_rsqrt(float x) {
    float y; asm("rsqrt.approx.ftz.f32 %0, %1;" : "=f"(y) : "f"(x)); return y;
}

__global__ void zero_kernel() {
    int idx = blockIdx.x * 256 + threadIdx.x;
    if (idx < SOD) {
        g_s[0][idx] = 0.f;
        g_s[1][idx] = 0.f;
        g_s[2][idx] = 0.f;
        g_Vsum[idx] = 0.f;
    }
}

// One routing pass. Grid (NIB, NBCH), block 1024 = 16 d x 64 b.
// Warp = fixed d, 32 consecutive batches -> W smem reads broadcast.
template<bool FIRST>
__global__ __launch_bounds__(1024, 2) void route_kernel(
    const float* __restrict__ x,   // [B, IC, ID]
    const float* __restrict__ W,   // [IC, OC, OD, ID]
    int which)
{
    extern __shared__ float sm[];
    float* Wsm = sm;                // [i][o][d][k]  20480
    float* Xsm = sm + W_TILE;       // [i][b][k]     8192

    const int t   = threadIdx.x;
    const int d   = t >> 6;         // 0..15
    const int bl  = t & 63;         // 0..63  (warp = same d, 32 b's)
    const int i0  = blockIdx.x * IBLK;
    const int b0  = blockIdx.y * BCH;

    // ---- cooperative W tile load (contiguous, coalesced) ----
    {
        const float4* src = reinterpret_cast<const float4*>(W + (size_t)i0 * (OC_ * OD_ * ID_));
        float4* dst = reinterpret_cast<float4*>(Wsm);
#pragma unroll
        for (int r = 0; r < W_TILE / 4 / 1024; r++)      // 5 iters
            dst[t + r * 1024] = src[t + r * 1024];
    }
    // ---- cooperative x tile load ----
    {
        float4* dst = reinterpret_cast<float4*>(Xsm);
#pragma unroll
        for (int r = 0; r < X_TILE / 4 / 1024; r++) {    // 2 iters
            int f = t + r * 1024;                        // 0..2047
            int b = f >> 5;                              // 0..63
            int c = f & 31;                              // float4 within b's block
            const float4* src = reinterpret_cast<const float4*>(
                x + ((size_t)(b0 + b) * IC_ + i0) * ID_);
            int i  = c >> 1;
            int h  = c & 1;
            dst[(i * BCH + b) * 2 + h] = src[c];
        }
    }
    __syncthreads();

    // ---- loop-invariant softmax logits vector ----
    float Vp[OC_];
    if (!FIRST) {
        const float* vp = g_Vs + ((size_t)(b0 + bl) * OD_ + d) * OC_;
#pragma unroll
        for (int o = 0; o < OC_; o++) Vp[o] = vp[o];
    }

    float s[OC_];
#pragma unroll
    for (int o = 0; o < OC_; o++) s[o] = 0.f;

    const float4* X4 = reinterpret_cast<const float4*>(Xsm);
    const float4* W4 = reinterpret_cast<const float4*>(Wsm);

#pragma unroll
    for (int i = 0; i < IBLK; i++) {
        float4 xa = X4[(i * BCH + bl) * 2];
        float4 xb = X4[(i * BCH + bl) * 2 + 1];

        float u[OC_];
#pragma unroll
        for (int o = 0; o < OC_; o++) {
            // broadcast LDS: all lanes in warp read same address
            float4 wa = W4[((i * OC_ + o) * OD_ + d) * 2];
            float4 wb = W4[((i * OC_ + o) * OD_ + d) * 2 + 1];
            float acc = wa.x * xa.x;
            acc = fmaf(wa.y, xa.y, acc);
            acc = fmaf(wa.z, xa.z, acc);
            acc = fmaf(wa.w, xa.w, acc);
            acc = fmaf(wb.x, xb.x, acc);
            acc = fmaf(wb.y, xb.y, acc);
            acc = fmaf(wb.z, xb.z, acc);
            acc = fmaf(wb.w, xb.w, acc);
            u[o] = acc;
        }

        if (FIRST) {
#pragma unroll
            for (int o = 0; o < OC_; o++) s[o] += u[o];
        } else {
            float e[OC_];
            float Z = 0.f;
#pragma unroll
            for (int o = 0; o < OC_; o++) {
                e[o] = fast_ex2(u[o] * Vp[o]);
                Z += e[o];
            }
            float r = fast_rcp(Z);
#pragma unroll
            for (int o = 0; o < OC_; o++) s[o] = fmaf(u[o], e[o] * r, s[o]);
        }
    }

    // accumulate partial s into global (72 i-block CTAs contend per element;
    // lanes hit distinct addresses -> spread REDG)
    float* sp = g_s[which] + ((size_t)(b0 + bl) * OD_ + d) * OC_;
#pragma unroll
    for (int o = 0; o < OC_; o++)
        atomicAdd(sp + o, FIRST ? s[o] * (1.0f / OC_) : s[o]);
}

// squash(s) per (b,o) over d; update Vsum / Vs, or write final output.
__global__ void squash_kernel(int which, float* __restrict__ out, int final_) {
    const float* __restrict__ s = g_s[which];
    int t  = blockIdx.x * 256 + threadIdx.x;   // SOD threads exactly
    int d  = t & 15;
    int bo = t >> 4;
    int o  = bo % OC_;
    int b  = bo / OC_;

    float sv = s[((size_t)b * OD_ + d) * OC_ + o];
    float l2 = sv * sv;
#pragma unroll
    for (int off = 8; off > 0; off >>= 1)
        l2 += __shfl_xor_sync(0xffffffffu, l2, off);

    float coef = l2 * fast_rsqrt(l2) * fast_rcp(1.f + l2);
    float v = sv * coef;

    if (final_) {
        out[((size_t)b * OC_ + o) * OD_ + d] = v;   // [B, OC, OD]
    } else {
        int idx = ((size_t)b * OD_ + d) * OC_ + o;
        float nv = g_Vsum[idx] + v;
        g_Vsum[idx] = nv;
        g_Vs[idx] = nv * 1.4426950408889634f;       // * log2(e)
    }
}

extern "C" void kernel_launch(void* const* d_in, const int* in_sizes, int n_in,
                              void* d_out, int out_size) {
    const float* x = (const float*)d_in[0];   // [256,1152,8]
    const float* W = (const float*)d_in[1];   // [1152,10,16,8]
    float* out = (float*)d_out;               // [256,10,16]

    cudaFuncSetAttribute(route_kernel<true>,
                         cudaFuncAttributeMaxDynamicSharedMemorySize, SMEMB);
    cudaFuncSetAttribute(route_kernel<false>,
                         cudaFuncAttributeMaxDynamicSharedMemorySize, SMEMB);

    dim3 rg(NIB, NBCH);
    int sgrid = SOD / 256;   // 160

    zero_kernel<<<sgrid, 256>>>();

    route_kernel<true><<<rg, 1024, SMEMB>>>(x, W, 0);
    squash_kernel<<<sgrid, 256>>>(0, out, 0);

    route_kernel<false><<<rg, 1024, SMEMB>>>(x, W, 1);
    squash_kernel<<<sgrid, 256>>>(1, out, 0);

    route_kernel<false><<<rg, 1024, SMEMB>>>(x, W, 2);
    squash_kernel<<<sgrid, 256>>>(2, out, 1);
}

// round 4
// speedup vs baseline: 1.6207x; 1.6207x over previous
#include <cuda_runtime.h>

// CapsNet dynamic routing, fused, shuffle-free, spill-free.
// b_t = u * Vsum so u (189 MB) is never materialized.
// Thread = (batch, d); loops over the CTA's 16 input-caps accumulating s[o]
// in registers. W tile broadcast from smem (warp = 32 b's, same d).

namespace {
constexpr int B_  = 256;
constexpr int IC_ = 1152;
constexpr int ID_ = 8;
constexpr int OC_ = 10;
constexpr int OD_ = 16;
constexpr int SOD = B_ * OD_ * OC_;   // 40960

constexpr int IBLK = 16;              // input caps per CTA
constexpr int BCH  = 32;              // batches per CTA
constexpr int NIB  = IC_ / IBLK;      // 72
constexpr int NBCH = B_ / BCH;        // 8
constexpr int NT   = 512;             // 16 d x 32 b

constexpr int W_TILE  = IBLK * OC_ * OD_ * ID_;   // 20480 floats (80 KB)
constexpr int X_TILE  = IBLK * BCH * ID_;         // 4096 floats  (16 KB)
constexpr int SMEMB   = (W_TILE + X_TILE) * 4;    // 98304 bytes
}

__device__ float g_s[3][SOD];    // s per iteration, layout [b][d][o]
__device__ float g_Vsum[SOD];    // running sum of v
__device__ float g_Vs[SOD];      // Vsum * log2(e)

__device__ __forceinline__ float fast_ex2(float x) {
    float y; asm("ex2.approx.ftz.f32 %0, %1;" : "=f"(y) : "f"(x)); return y;
}
__device__ __forceinline__ float fast_rcp(float x) {
    float y; asm("rcp.approx.ftz.f32 %0, %1;" : "=f"(y) : "f"(x)); return y;
}
__device__ __forceinline__ float fast_rsqrt(float x) {
    float y; asm("rsqrt.approx.ftz.f32 %0, %1;" : "=f"(y) : "f"(x)); return y;
}

__global__ void zero_kernel() {
    int idx = blockIdx.x * 256 + threadIdx.x;
    if (idx < SOD) {
        g_s[0][idx] = 0.f;
        g_s[1][idx] = 0.f;
        g_s[2][idx] = 0.f;
        g_Vsum[idx] = 0.f;
    }
}

// One routing pass. Grid (NIB, NBCH), block 512 = 16 d x 32 b.
// Warp = fixed d, 32 batches -> every W smem read is a broadcast.
template<bool FIRST>
__global__ __launch_bounds__(NT) void route_kernel(
    const float* __restrict__ x,   // [B, IC, ID]
    const float* __restrict__ W,   // [IC, OC, OD, ID]
    int which)
{
    extern __shared__ float sm[];
    float* Wsm = sm;                // [i][o][d][k]        20480 floats
    float* Xsm = sm + W_TILE;       // [h][i][b] float4s   4096 floats

    const int t   = threadIdx.x;
    const int d   = t >> 5;         // 0..15
    const int bl  = t & 31;         // 0..31 (= lane)
    const int i0  = blockIdx.x * IBLK;
    const int b0  = blockIdx.y * BCH;

    // ---- cooperative W tile load (contiguous, coalesced) ----
    {
        const float4* src = reinterpret_cast<const float4*>(
            W + (size_t)i0 * (OC_ * OD_ * ID_));
        float4* dst = reinterpret_cast<float4*>(Wsm);
#pragma unroll
        for (int r = 0; r < W_TILE / 4 / NT; r++)        // 10 iters
            dst[t + r * NT] = src[t + r * NT];
    }
    // ---- cooperative x tile load, layout [h][i][b] of float4 ----
    {
        float4* dst = reinterpret_cast<float4*>(Xsm);
#pragma unroll
        for (int r = 0; r < X_TILE / 4 / NT; r++) {      // 2 iters
            int f = t + r * NT;                          // 0..1023
            int b = f >> 5;                              // 0..31
            int c = f & 31;                              // float4 within b row
            const float4* src = reinterpret_cast<const float4*>(
                x + ((size_t)(b0 + b) * IC_ + i0) * ID_);
            int i = c >> 1;
            int h = c & 1;
            dst[h * (IBLK * BCH) + i * BCH + b] = src[c];
        }
    }
    __syncthreads();

    // loop-invariant softmax logit scale (Vsum * log2e), per (b,d)
    float Vp[OC_];
    if (!FIRST) {
        const float* vp = g_Vs + ((size_t)(b0 + bl) * OD_ + d) * OC_;
#pragma unroll
        for (int o = 0; o < OC_; o++) Vp[o] = vp[o];
    }

    float s[OC_];
#pragma unroll
    for (int o = 0; o < OC_; o++) s[o] = 0.f;

    const float4* X4 = reinterpret_cast<const float4*>(Xsm);
    const float4* W4 = reinterpret_cast<const float4*>(Wsm);

#pragma unroll 4
    for (int i = 0; i < IBLK; i++) {
        float4 xa = X4[i * BCH + bl];                       // conflict-free
        float4 xb = X4[IBLK * BCH + i * BCH + bl];

        float u[OC_];
#pragma unroll
        for (int o = 0; o < OC_; o++) {
            // broadcast LDS: all lanes read same address
            float4 wa = W4[((i * OC_ + o) * OD_ + d) * 2];
            float4 wb = W4[((i * OC_ + o) * OD_ + d) * 2 + 1];
            float acc = wa.x * xa.x;
            acc = fmaf(wa.y, xa.y, acc);
            acc = fmaf(wa.z, xa.z, acc);
            acc = fmaf(wa.w, xa.w, acc);
            acc = fmaf(wb.x, xb.x, acc);
            acc = fmaf(wb.y, xb.y, acc);
            acc = fmaf(wb.z, xb.z, acc);
            acc = fmaf(wb.w, xb.w, acc);
            u[o] = acc;
        }

        if (FIRST) {
#pragma unroll
            for (int o = 0; o < OC_; o++) s[o] += u[o];
        } else {
            float Z = 0.f;
#pragma unroll
            for (int o = 0; o < OC_; o++) {
                float e = fast_ex2(u[o] * Vp[o]);
                Z += e;
                u[o] *= e;                  // u now holds u*e (p)
            }
            float r = fast_rcp(Z);
#pragma unroll
            for (int o = 0; o < OC_; o++) s[o] = fmaf(u[o], r, s[o]);
        }
    }

    // accumulate partial s into global (lanes hit distinct addresses)
    float* sp = g_s[which] + ((size_t)(b0 + bl) * OD_ + d) * OC_;
#pragma unroll
    for (int o = 0; o < OC_; o++)
        atomicAdd(sp + o, FIRST ? s[o] * (1.0f / OC_) : s[o]);
}

// squash(s) per (b,o) over d; update Vsum / Vs, or write final output.
__global__ void squash_kernel(int which, float* __restrict__ out, int final_) {
    const float* __restrict__ s = g_s[which];
    int t  = blockIdx.x * 256 + threadIdx.x;   // SOD threads exactly
    int d  = t & 15;
    int bo = t >> 4;
    int o  = bo % OC_;
    int b  = bo / OC_;

    float sv = s[((size_t)b * OD_ + d) * OC_ + o];
    float l2 = sv * sv;
#pragma unroll
    for (int off = 8; off > 0; off >>= 1)
        l2 += __shfl_xor_sync(0xffffffffu, l2, off);

    float coef = l2 * fast_rsqrt(l2) * fast_rcp(1.f + l2);
    float v = sv * coef;

    if (final_) {
        out[((size_t)b * OC_ + o) * OD_ + d] = v;   // [B, OC, OD]
    } else {
        int idx = ((size_t)b * OD_ + d) * OC_ + o;
        float nv = g_Vsum[idx] + v;
        g_Vsum[idx] = nv;
        g_Vs[idx] = nv * 1.4426950408889634f;       // * log2(e)
    }
}

extern "C" void kernel_launch(void* const* d_in, const int* in_sizes, int n_in,
                              void* d_out, int out_size) {
    const float* x = (const float*)d_in[0];   // [256,1152,8]
    const float* W = (const float*)d_in[1];   // [1152,10,16,8]
    float* out = (float*)d_out;               // [256,10,16]

    cudaFuncSetAttribute(route_kernel<true>,
                         cudaFuncAttributeMaxDynamicSharedMemorySize, SMEMB);
    cudaFuncSetAttribute(route_kernel<false>,
                         cudaFuncAttributeMaxDynamicSharedMemorySize, SMEMB);

    dim3 rg(NIB, NBCH);
    int sgrid = SOD / 256;   // 160

    zero_kernel<<<sgrid, 256>>>();

    route_kernel<true><<<rg, NT, SMEMB>>>(x, W, 0);
    squash_kernel<<<sgrid, 256>>>(0, out, 0);

    route_kernel<false><<<rg, NT, SMEMB>>>(x, W, 1);
    squash_kernel<<<sgrid, 256>>>(1, out, 0);

    route_kernel<false><<<rg, NT, SMEMB>>>(x, W, 2);
    squash_kernel<<<sgrid, 256>>>(2, out, 1);
}

// round 5
// speedup vs baseline: 2.5741x; 1.5882x over previous
#include <cuda_runtime.h>

// CapsNet dynamic routing, fused, f32x2-packed over the OD dimension.
// b_t = u * Vsum so u (189 MB) is never materialized.
// Thread = (batch, d-pair); loops 32 input-caps in 2 smem chunks, accumulating
// s[o] (f32x2) in registers. W pre-transposed so LDS.128 yields packed pairs.

namespace {
constexpr int B_  = 256;
constexpr int IC_ = 1152;
constexpr int ID_ = 8;
constexpr int OC_ = 10;
constexpr int OD_ = 16;
constexpr int SOD = B_ * OC_ * OD_;   // 40960, layout [b][o][d]

constexpr int IBLK = 16;              // i's per smem chunk
constexpr int NCHK = 2;               // chunks per CTA
constexpr int BCH  = 64;              // batches per CTA
constexpr int NT   = 512;             // 8 dpairs x 64 b
constexpr int GX   = IC_ / (IBLK * NCHK);  // 36
constexpr int GY   = B_ / BCH;             // 4

constexpr int W_TILE_F = IBLK * OC_ * OD_ * ID_;  // 20480 floats (80 KB)
constexpr int XI = 65;                 // float4 stride over i (padded)
constexpr int XH = 1040;               // float4 stride over k-half
constexpr int X_TILE_F4 = 2 * XH;      // 2080 float4
constexpr int SMEMB = W_TILE_F * 4 + X_TILE_F4 * 16;  // 115200 B
constexpr int WT_ELEMS = IC_ * OC_ * OD_ * ID_;       // 1474560
}

typedef unsigned long long ull;

__device__ __align__(16) float g_Wt[WT_ELEMS];  // [i][o][dp][k][dl]
__device__ __align__(16) float g_s[3][SOD];     // [b][o][d]
__device__ __align__(16) float g_Vsum[SOD];
__device__ __align__(16) float g_Vs[SOD];       // Vsum * log2(e)

__device__ __forceinline__ float fast_ex2(float x) {
    float y; asm("ex2.approx.ftz.f32 %0, %1;" : "=f"(y) : "f"(x)); return y;
}
__device__ __forceinline__ float fast_rcp(float x) {
    float y; asm("rcp.approx.ftz.f32 %0, %1;" : "=f"(y) : "f"(x)); return y;
}
__device__ __forceinline__ float fast_rsqrt(float x) {
    float y; asm("rsqrt.approx.ftz.f32 %0, %1;" : "=f"(y) : "f"(x)); return y;
}
__device__ __forceinline__ ull pack2(float lo, float hi) {
    ull r; asm("mov.b64 %0, {%1, %2};" : "=l"(r) : "f"(lo), "f"(hi)); return r;
}
__device__ __forceinline__ void unpack2(ull v, float& lo, float& hi) {
    asm("mov.b64 {%0, %1}, %2;" : "=f"(lo), "=f"(hi) : "l"(v));
}
__device__ __forceinline__ ull fma2(ull a, ull b, ull c) {
    ull d; asm("fma.rn.f32x2 %0, %1, %2, %3;" : "=l"(d) : "l"(a), "l"(b), "l"(c)); return d;
}
__device__ __forceinline__ ull mul2(ull a, ull b) {
    ull d; asm("mul.rn.f32x2 %0, %1, %2;" : "=l"(d) : "l"(a), "l"(b)); return d;
}
__device__ __forceinline__ ull add2(ull a, ull b) {
    ull d; asm("add.rn.f32x2 %0, %1, %2;" : "=l"(d) : "l"(a), "l"(b)); return d;
}

// Transpose W[i][o][d][k] -> g_Wt[i][o][dp][k][dl]  (dl = d&1)
__global__ void prepack_kernel(const float* __restrict__ W) {
    int e = blockIdx.x * NT + threadIdx.x;
    if (e >= WT_ELEMS) return;
    int io = e >> 7;          // 128 floats per (i,o)
    int r  = e & 127;
    int dp = r >> 4;
    int k  = (r >> 1) & 7;
    int dl = r & 1;
    g_Wt[e] = W[(io * OD_ + 2 * dp + dl) * ID_ + k];
}

__global__ void zero_kernel() {
    int idx = blockIdx.x * 256 + threadIdx.x;
    if (idx < SOD) {
        g_s[0][idx] = 0.f;
        g_s[1][idx] = 0.f;
        g_s[2][idx] = 0.f;
        g_Vsum[idx] = 0.f;
    }
}

// Routing pass. Grid (36, 4), block 512 = 8 dpair x 64 b.
// Warp = fixed dpair, 32 batches -> every W smem read is a broadcast.
template<bool FIRST>
__global__ __launch_bounds__(NT) void route_kernel(
    const float* __restrict__ x,   // [B, IC, ID]
    int which)
{
    extern __shared__ float sm[];
    float* Wsm = sm;                              // 20480 floats
    float4* X4 = reinterpret_cast<float4*>(sm + W_TILE_F);  // [h][i(pad)][b]

    const int t   = threadIdx.x;
    const int dp  = t >> 6;         // 0..7
    const int bl  = t & 63;         // 0..63 (warp: 32 consecutive bl, same dp)
    const int b   = blockIdx.y * BCH + bl;

    // loop-invariant softmax logit scale pairs (Vsum*log2e for d=2dp,2dp+1)
    ull Vp[OC_];
    if (!FIRST) {
#pragma unroll
        for (int o = 0; o < OC_; o++)
            Vp[o] = *reinterpret_cast<const ull*>(
                g_Vs + (((size_t)b * OC_ + o) * OD_ + 2 * dp));
    }

    ull s[OC_];
    const ull zz = pack2(0.f, 0.f);
#pragma unroll
    for (int o = 0; o < OC_; o++) s[o] = zz;

    for (int c = 0; c < NCHK; c++) {
        const int i0 = blockIdx.x * (IBLK * NCHK) + c * IBLK;
        if (c) __syncthreads();     // drain readers of previous tiles

        // ---- W tile: straight copy of pre-transposed weights ----
        {
            const float4* src = reinterpret_cast<const float4*>(
                g_Wt + (size_t)i0 * (OC_ * OD_ * ID_));
            float4* dst = reinterpret_cast<float4*>(Wsm);
#pragma unroll
            for (int r = 0; r < W_TILE_F / 4 / NT; r++)   // 10
                dst[t + r * NT] = src[t + r * NT];
        }
        // ---- x tile: [h][i][b] float4, padded strides ----
        {
#pragma unroll
            for (int r = 0; r < 4; r++) {
                int f = t + r * NT;                       // 0..2047
                int bb = f >> 5;                          // 0..63
                int cc = f & 31;
                const float4* src = reinterpret_cast<const float4*>(
                    x + ((size_t)(blockIdx.y * BCH + bb) * IC_ + i0) * ID_);
                int i = cc >> 1, h = cc & 1;
                X4[h * XH + i * XI + bb] = src[cc];
            }
        }
        __syncthreads();

        const ulonglong2* W2 = reinterpret_cast<const ulonglong2*>(Wsm);

#pragma unroll 4
        for (int i = 0; i < IBLK; i++) {
            float4 xa = X4[i * XI + bl];
            float4 xb = X4[XH + i * XI + bl];
            ull xp[ID_];
            xp[0] = pack2(xa.x, xa.x); xp[1] = pack2(xa.y, xa.y);
            xp[2] = pack2(xa.z, xa.z); xp[3] = pack2(xa.w, xa.w);
            xp[4] = pack2(xb.x, xb.x); xp[5] = pack2(xb.y, xb.y);
            xp[6] = pack2(xb.z, xb.z); xp[7] = pack2(xb.w, xb.w);

            ull u[OC_];
#pragma unroll
            for (int o = 0; o < OC_; o++) {
                // broadcast LDS.128: two packed W pairs each
                int wb = ((i * OC_ + o) * ID_ + dp) * 4;
                ulonglong2 w01 = W2[wb];
                ulonglong2 w23 = W2[wb + 1];
                ulonglong2 w45 = W2[wb + 2];
                ulonglong2 w67 = W2[wb + 3];
                ull acc = mul2(w01.x, xp[0]);
                acc = fma2(w01.y, xp[1], acc);
                acc = fma2(w23.x, xp[2], acc);
                acc = fma2(w23.y, xp[3], acc);
                acc = fma2(w45.x, xp[4], acc);
                acc = fma2(w45.y, xp[5], acc);
                acc = fma2(w67.x, xp[6], acc);
                acc = fma2(w67.y, xp[7], acc);
                u[o] = acc;
            }

            if (FIRST) {
#pragma unroll
                for (int o = 0; o < OC_; o++) s[o] = add2(s[o], u[o]);
            } else {
                ull Z2 = zz;
#pragma unroll
                for (int o = 0; o < OC_; o++) {
                    ull lg = mul2(u[o], Vp[o]);
                    float l0, l1; unpack2(lg, l0, l1);
                    ull ep = pack2(fast_ex2(l0), fast_ex2(l1));
                    Z2 = add2(Z2, ep);
                    u[o] = mul2(u[o], ep);        // u now holds u*e
                }
                float Z0, Z1; unpack2(Z2, Z0, Z1);
                ull rp = pack2(fast_rcp(Z0), fast_rcp(Z1));
#pragma unroll
                for (int o = 0; o < OC_; o++) s[o] = fma2(u[o], rp, s[o]);
            }
        }
    }

    // accumulate partial s into global [b][o][d]
    float* sp = g_s[which] + ((size_t)b * OC_) * OD_ + 2 * dp;
#pragma unroll
    for (int o = 0; o < OC_; o++) {
        float a0, a1; unpack2(s[o], a0, a1);
        if (FIRST) { a0 *= (1.0f / OC_); a1 *= (1.0f / OC_); }
        atomicAdd(sp + o * OD_, a0);
        atomicAdd(sp + o * OD_ + 1, a1);
    }
}

// squash(s) per (b,o) over d; update Vsum / Vs, or write final output.
__global__ void squash_kernel(int which, float* __restrict__ out, int final_) {
    const float* __restrict__ s = g_s[which];
    int t  = blockIdx.x * 256 + threadIdx.x;   // SOD threads exactly
    int d  = t & 15;
    int bo = t >> 4;
    int idx = bo * OD_ + d;                    // [b][o][d]

    float sv = s[idx];
    float l2 = sv * sv;
#pragma unroll
    for (int off = 8; off > 0; off >>= 1)
        l2 += __shfl_xor_sync(0xffffffffu, l2, off);

    float coef = l2 * fast_rsqrt(l2) * fast_rcp(1.f + l2);
    float v = sv * coef;

    if (final_) {
        out[idx] = v;                           // output [B, OC, OD]
    } else {
        float nv = g_Vsum[idx] + v;
        g_Vsum[idx] = nv;
        g_Vs[idx] = nv * 1.4426950408889634f;   // * log2(e)
    }
}

extern "C" void kernel_launch(void* const* d_in, const int* in_sizes, int n_in,
                              void* d_out, int out_size) {
    const float* x = (const float*)d_in[0];   // [256,1152,8]
    const float* W = (const float*)d_in[1];   // [1152,10,16,8]
    float* out = (float*)d_out;               // [256,10,16]

    cudaFuncSetAttribute(route_kernel<true>,
                         cudaFuncAttributeMaxDynamicSharedMemorySize, SMEMB);
    cudaFuncSetAttribute(route_kernel<false>,
                         cudaFuncAttributeMaxDynamicSharedMemorySize, SMEMB);

    dim3 rg(GX, GY);
    int sgrid = SOD / 256;   // 160

    prepack_kernel<<<(WT_ELEMS + NT - 1) / NT, NT>>>(W);
    zero_kernel<<<sgrid, 256>>>();

    route_kernel<true><<<rg, NT, SMEMB>>>(x, 0);
    squash_kernel<<<sgrid, 256>>>(0, out, 0);

    route_kernel<false><<<rg, NT, SMEMB>>>(x, 1);
    squash_kernel<<<sgrid, 256>>>(1, out, 0);

    route_kernel<false><<<rg, NT, SMEMB>>>(x, 2);
    squash_kernel<<<sgrid, 256>>>(2, out, 1);
}